// round 9
// baseline (speedup 1.0000x reference)
#include <cuda_runtime.h>
#include <math.h>

// ---------------------------------------------------------------------------
// Factorized radial-basis CNN. R9 = R6 conv kernels (best known) with:
//  - conv1: 3-deep cp.async ring -> single __syncthreads per ci iteration.
//  - tail_kernel: kS + head fused (one launch), double-buffered ci streaming,
//    warp-parallel B-contraction.
// ---------------------------------------------------------------------------

#define PZ 39
#define PX 40
#define PLANE (PZ*PZ*PX)      // 60840 floats per (b,ci) act0 plane

__device__ float g_act0[16*20*PLANE];    // zero-init => halo+pad stay 0
__device__ float g_act1[16*20*18*18*18];

struct BC { float b[30]; };      // [j*10 + orbit]
struct BF { float b[3][128]; };  // full per-tap basis [j][tap0..124]

__host__ __device__ constexpr int orbit_of(int tz, int ty, int tx) {
    int dz = tz - 2, dy = ty - 2, dx = tx - 2;
    int r2 = dz*dz + dy*dy + dx*dx;            // {0..6, 8, 9, 12}
    return r2 <= 6 ? r2 : (r2 == 8 ? 7 : (r2 == 9 ? 8 : 9));
}

__device__ __forceinline__ void cp_async16(float* dst, const float* src) {
    unsigned int d = (unsigned int)__cvta_generic_to_shared(dst);
    asm volatile("cp.async.cg.shared.global [%0], [%1], 16;" :: "r"(d), "l"(src));
}

// ---------------------------------------------------------------------------
// conv0: CIN=1, 64^3 -> 33^3 into padded [39,39,40]. Tile (9z,3y,33x),
// 297 threads; thread: ox=tid%33, oy=(tid/33)%3, zg=tid/99; 3 z-outputs (p).
// (byte-for-byte R6)
// ---------------------------------------------------------------------------
__global__ void __launch_bounds__(297)
conv0_kernel(const float* __restrict__ in, const float* __restrict__ W,
             float* __restrict__ out, BC Bc)
{
    extern __shared__ float sm0[];
    float* sIn = sm0;              // 21 z x 9 y x 70 x = 13230
    float* sW  = sm0 + 13232;      // 72, 16B-aligned
    float* sB  = sW + 72;          // 30

    const int tid = threadIdx.x;
    const int b   = blockIdx.y;
    const int zt  = blockIdx.x / 11, yt = blockIdx.x % 11;
    const int oz0 = 9*zt, oy0 = 3*yt;

    if (tid < 72) { int j = tid/24, o = tid%24; sW[tid] = (o < 23) ? W[o*3 + j] : 0.f; }
    if (tid < 30) sB[tid] = Bc.b[tid];

    const float* gin = in + (long)b * (64*64*64);
    for (int idx = tid; idx < 21*9*70; idx += 297) {
        int iz = idx / 630, r = idx % 630, iy = r / 70, ix = r % 70;
        int gz = 2*oz0 - 3 + iz, gy = 2*oy0 - 3 + iy, gx = ix - 3;
        float v = 0.f;
        if (ix < 69 && (unsigned)gz < 64u && (unsigned)gy < 64u && (unsigned)gx < 64u)
            v = gin[(gz*64 + gy)*64 + gx];
        sIn[idx] = v;
    }
    __syncthreads();

    const int ox = tid % 33;
    const int r0 = tid / 33;
    const int oy = r0 % 3;
    const int zg = r0 / 3;         // 0..2; thread's z-outputs: oz0+3*zg+p

    float T[3][10];
#pragma unroll
    for (int p = 0; p < 3; p++)
#pragma unroll
        for (int g = 0; g < 10; g++) T[p][g] = 0.f;

#pragma unroll
    for (int s = 0; s < 9; s++) {          // iz = 6*zg + s ; tz = s - 2p
#pragma unroll
        for (int ty = 0; ty < 5; ty++) {
            const float2* rp = (const float2*)
                &sIn[((6*zg + s)*9 + (2*oy + ty))*70 + 2*ox];
            float2 c0 = rp[0], c1 = rp[1], c2 = rp[2];
            float v0 = c0.x, v1 = c0.y, v2 = c1.x, v3 = c1.y, v4 = c2.x;
#pragma unroll
            for (int p = 0; p < 3; p++) {
                const int tz = s - 2*p;
                if (tz >= 0 && tz <= 4) {
                    T[p][orbit_of(tz, ty, 0)] += v0;
                    T[p][orbit_of(tz, ty, 1)] += v1;
                    T[p][orbit_of(tz, ty, 2)] += v2;
                    T[p][orbit_of(tz, ty, 3)] += v3;
                    T[p][orbit_of(tz, ty, 4)] += v4;
                }
            }
        }
    }

    float U[3][3] = {};
#pragma unroll
    for (int j = 0; j < 3; j++)
#pragma unroll
    for (int g = 0; g < 10; g++) {
        float bv = sB[j*10 + g];
        U[0][j] = fmaf(bv, T[0][g], U[0][j]);
        U[1][j] = fmaf(bv, T[1][g], U[1][j]);
        U[2][j] = fmaf(bv, T[2][g], U[2][j]);
    }

    const float4* w4 = (const float4*)sW;
    float* gout = out + (long)b * 20 * PLANE;
#pragma unroll
    for (int p = 0; p < 3; p++) {
        const int oz = oz0 + 3*zg + p;
        if (oz > 32) continue;
        float y[24];
#pragma unroll
        for (int c = 0; c < 24; c++) y[c] = 0.f;
#pragma unroll
        for (int j = 0; j < 3; j++)
#pragma unroll
        for (int q = 0; q < 6; q++) {
            float4 w = w4[j*6 + q];
            y[q*4+0] = fmaf(U[p][j], w.x, y[q*4+0]);
            y[q*4+1] = fmaf(U[p][j], w.y, y[q*4+1]);
            y[q*4+2] = fmaf(U[p][j], w.z, y[q*4+2]);
            y[q*4+3] = fmaf(U[p][j], w.w, y[q*4+3]);
        }
        float g0 = 1.f/(1.f + expf(-y[20]));
        float g1 = 1.f/(1.f + expf(-y[21]));
        float g2 = 1.f/(1.f + expf(-y[22]));
#pragma unroll
        for (int oc = 0; oc < 20; oc++) {
            float v = (oc < 5) ? fmaxf(y[oc], 0.f)
                               : y[oc] * (oc < 8 ? g0 : (oc < 13 ? g1 : g2));
            gout[((long)oc*PZ + (oz+3))*(PZ*PX) + (oy0+oy+3)*PX + (ox+3)] = v;
        }
    }
}

// ---------------------------------------------------------------------------
// conv1: CIN=20, act0 [39,39,40] -> 18^3. Tile (6z,6y,18x), 648 threads,
// 1 z-output/thread. 3-deep cp.async ring -> ONE barrier per ci iteration.
// ---------------------------------------------------------------------------
__global__ void __launch_bounds__(648, 1)
conv1_kernel(const float* __restrict__ in, const float* __restrict__ W,
             float* __restrict__ out, BC Bc)
{
    constexpr int NT = 648, SLAB = 600, NSLAB = 15;
    extern __shared__ float dsm[];
    float* raw0 = dsm;
    float* raw1 = dsm + 9000;
    float* raw2 = dsm + 18000;
    float* sW = dsm + 27000;                  // 1440, 16B-aligned
    float* sB = sW + 1440;                    // 30

    const int tid = threadIdx.x;
    const int b   = blockIdx.y;
    const int zt  = blockIdx.x / 3, yt = blockIdx.x % 3;
    const int oz0 = 6*zt, oy0 = 6*yt;

    for (int idx = tid; idx < 1440; idx += NT) {
        int ci = idx / 72, r = idx % 72, j = r / 24, o = r % 24;
        sW[idx] = (o < 23) ? W[(o*20 + ci)*3 + j] : 0.f;
    }
    if (tid < 30) sB[tid] = Bc.b[tid];

    const int ox  = tid % 18;
    const int r0  = tid / 18;
    const int oy  = r0 % 6;
    const int ozl = r0 / 6;        // 0..5

    float acc[24];
#pragma unroll
    for (int c = 0; c < 24; c++) acc[c] = 0.f;

    float* bufs[3] = { raw0, raw1, raw2 };

    // 15 slabs; each: 15 y-rows x 40 = 600 contiguous floats in BOTH layouts
    auto issue = [&](int ci, float* dst) {
        const float* g = in + (long)(b*20 + ci)*PLANE
                            + (2*oz0)*(PZ*PX) + (2*oy0)*PX;
        for (int idx = tid; idx < NSLAB*150; idx += NT) {   // 16B ops
            int iz = idx / 150, k = idx % 150;
            cp_async16(dst + iz*SLAB + 4*k, g + iz*(PZ*PX) + 4*k);
        }
        asm volatile("cp.async.commit_group;");
    };

    issue(0, bufs[0]);
    issue(1, bufs[1]);
    for (int ci = 0; ci < 20; ci++) {
        float* cur = bufs[ci % 3];
        if (ci < 19) { asm volatile("cp.async.wait_group 1;"); }
        else         { asm volatile("cp.async.wait_group 0;"); }
        __syncthreads();               // cur visible; also fences prior reads
                                       // of bufs[(ci+2)%3] (last read ci-1)

        float T[10];
#pragma unroll
        for (int g = 0; g < 10; g++) T[g] = 0.f;

#pragma unroll
        for (int tz = 0; tz < 5; tz++) {
#pragma unroll
            for (int ty = 0; ty < 5; ty++) {
                const float2* rp = (const float2*)
                    &cur[(2*ozl + tz)*SLAB + (2*oy + ty)*PX + 2*ox];
                float2 c0 = rp[0], c1 = rp[1], c2 = rp[2];
                T[orbit_of(tz, ty, 0)] += c0.x;
                T[orbit_of(tz, ty, 1)] += c0.y;
                T[orbit_of(tz, ty, 2)] += c1.x;
                T[orbit_of(tz, ty, 3)] += c1.y;
                T[orbit_of(tz, ty, 4)] += c2.x;
            }
        }

        float U[3] = {};
#pragma unroll
        for (int j = 0; j < 3; j++)
#pragma unroll
        for (int g = 0; g < 10; g++)
            U[j] = fmaf(sB[j*10 + g], T[g], U[j]);

        const float4* w4 = (const float4*)&sW[ci*72];
#pragma unroll
        for (int j = 0; j < 3; j++)
#pragma unroll
        for (int q = 0; q < 6; q++) {
            float4 w = w4[j*6 + q];
            acc[q*4+0] = fmaf(U[j], w.x, acc[q*4+0]);
            acc[q*4+1] = fmaf(U[j], w.y, acc[q*4+1]);
            acc[q*4+2] = fmaf(U[j], w.z, acc[q*4+2]);
            acc[q*4+3] = fmaf(U[j], w.w, acc[q*4+3]);
        }

        if (ci + 2 < 20) issue(ci + 2, bufs[(ci + 2) % 3]);
    }

    float* gout = out + (long)b * 20 * 5832;
    const int oz = oz0 + ozl;
    float g0 = 1.f/(1.f + expf(-acc[20]));
    float g1 = 1.f/(1.f + expf(-acc[21]));
    float g2 = 1.f/(1.f + expf(-acc[22]));
#pragma unroll
    for (int oc = 0; oc < 20; oc++) {
        float y = acc[oc];
        float v = (oc < 5) ? fmaxf(y, 0.f)
                           : y * (oc < 8 ? g0 : (oc < 13 ? g1 : g2));
        gout[((long)oc*18 + oz)*324 + (oy0 + oy)*18 + ox] = v;
    }
}

// ---------------------------------------------------------------------------
// tail: fused kS + head. Grid 16 (one block per batch), 256 threads.
// Per ci: two-stage separable tap reduction -> sS[125]; warp-parallel
// B-contraction -> sV[ci*3+j]. Then pooled/fc1/fc2.
// ---------------------------------------------------------------------------
__global__ void __launch_bounds__(256)
tail_kernel(const float* __restrict__ act, const float* __restrict__ W2,
            const float* __restrict__ fc1w, const float* __restrict__ fc1b,
            const float* __restrict__ fc2w, const float* __restrict__ fc2b,
            float* __restrict__ out, BF bf)
{
    extern __shared__ float dsm[];
    float* s0  = dsm;            // 5832
    float* s1  = dsm + 5832;     // 5832
    float* R   = dsm + 11664;    // 1620
    float* sS  = dsm + 13284;    // 128
    float* sV  = dsm + 13412;    // 60 (+pad 4)
    float* sW2 = dsm + 13476;    // 1380
    float* sF1 = dsm + 14856;    // 1000
    float* pooled = dsm + 15856; // 20
    float* h1  = dsm + 15876;    // 50

    const int b  = blockIdx.x;
    const int t  = threadIdx.x;  // 256
    float* bufs[2] = { s0, s1 };

    auto issue = [&](int ci, float* dst) {
        const float* g = act + (long)(b*20 + ci) * 5832;
        for (int k = t; k < 1458; k += 256)       // 5832/4 16B ops
            cp_async16(dst + 4*k, g + 4*k);
        asm volatile("cp.async.commit_group;");
    };

    issue(0, s0);
    // weight preload overlaps first act tile
    for (int i = t; i < 1380; i += 256) sW2[i] = W2[i];
    for (int i = t; i < 1000; i += 256) sF1[i] = fc1w[i];

    for (int ci = 0; ci < 20; ci++) {
        float* s = bufs[ci & 1];
        if (ci + 1 < 20) {
            issue(ci + 1, bufs[(ci + 1) & 1]);
            asm volatile("cp.async.wait_group 1;");
        } else {
            asm volatile("cp.async.wait_group 0;");
        }
        __syncthreads();

        // stage1: R[z][y][tx] = sum over valid ox of s[z][y][2ox+tx-3]
        for (int idx = t; idx < 1620; idx += 256) {
            int z = idx / 90, r = idx % 90, y = r / 5, tx = r % 5;
            int lo = (3 - tx + 1) >> 1; if (lo < 0) lo = 0;
            int hi = (20 - tx) >> 1;    if (hi > 9) hi = 9;
            float sum = 0.f;
            const float* row = &s[(z*18 + y)*18];
            for (int oxx = lo; oxx <= hi; oxx++) sum += row[2*oxx + tx - 3];
            R[idx] = sum;
        }
        __syncthreads();

        // stage2: sS[t] over valid (oz,oy)
        if (t < 125) {
            int tz = t / 25, ty = (t / 5) % 5, tx = t % 5;
            int loz = (3 - tz + 1) >> 1; if (loz < 0) loz = 0;
            int hiz = (20 - tz) >> 1;    if (hiz > 9) hiz = 9;
            int loy = (3 - ty + 1) >> 1; if (loy < 0) loy = 0;
            int hiy = (20 - ty) >> 1;    if (hiy > 9) hiy = 9;
            float sum = 0.f;
            for (int oz = loz; oz <= hiz; oz++) {
                int z = 2*oz + tz - 3;
                for (int oyy = loy; oyy <= hiy; oyy++)
                    sum += R[(z*18 + (2*oyy + ty - 3))*5 + tx];
            }
            sS[t] = sum;
        }
        __syncthreads();

        // stage3: warp-parallel B-contraction (3 warps, one per j)
        if (t < 96) {
            int j = t / 32, lane = t % 32;
            float a = 0.f;
#pragma unroll
            for (int k = 0; k < 4; k++) {
                int tap = lane + 32*k;
                if (tap < 125) a = fmaf(bf.b[j][tap], sS[tap], a);
            }
#pragma unroll
            for (int off = 16; off > 0; off >>= 1)
                a += __shfl_down_sync(0xffffffffu, a, off);
            if (lane == 0) sV[ci*3 + j] = a;
        }
        __syncthreads();   // sS/R reuse next iteration
    }

    // head
    if (t < 20) {
        float a = 0.f;
        for (int k = 0; k < 60; k++)
            a = fmaf(sW2[t*60 + k], sV[k], a);
        pooled[t] = a * (1.0f/1000.0f);
    }
    __syncthreads();
    if (t < 50) {
        float a = fc1b[t];
        for (int k = 0; k < 20; k++)
            a = fmaf(pooled[k], sF1[t*20 + k], a);
        h1[t] = fmaxf(a, 0.f);
    }
    __syncthreads();
    if (t < 2) {
        float a = fc2b[t];
        for (int k = 0; k < 50; k++)
            a = fmaf(h1[k], fc2w[t*50 + k], a);
        out[b*2 + t] = a;
    }
}

// ---------------------------------------------------------------------------
extern "C" void kernel_launch(void* const* d_in, const int* in_sizes, int n_in,
                              void* d_out, int out_size) {
    const float* inp  = (const float*)d_in[0];
    const float* W0   = (const float*)d_in[1];
    const float* W1   = (const float*)d_in[2];
    const float* W2   = (const float*)d_in[3];
    const float* fc1w = (const float*)d_in[4];
    const float* fc1b = (const float*)d_in[5];
    const float* fc2w = (const float*)d_in[6];
    const float* fc2b = (const float*)d_in[7];
    float* out = (float*)d_out;

    BC bc; BF bf;
    {
        const double r2s[10]  = {0,1,2,3,4,5,6,8,9,12};
        const double mult[10] = {1,6,12,8,6,24,24,12,24,8};
        for (int j = 0; j < 3; j++) {
            double v[10], sm = 0.0;
            for (int g = 0; g < 10; g++) {
                double d = (sqrt(r2s[g]) - (double)j) / 0.6;
                v[g] = exp(-0.5 * d * d);
                sm += mult[g] * v[g] * v[g];
            }
            double inv = 1.0 / sqrt(sm);
            for (int g = 0; g < 10; g++) bc.b[j*10 + g] = (float)(v[g] * inv);
            for (int tap = 0; tap < 128; tap++) {
                if (tap < 125) {
                    int tz = tap / 25, ty = (tap / 5) % 5, tx = tap % 5;
                    bf.b[j][tap] = bc.b[j*10 + orbit_of(tz, ty, tx)];
                } else bf.b[j][tap] = 0.f;
            }
        }
    }

    float *gA0, *gA1;
    cudaGetSymbolAddress((void**)&gA0, g_act0);
    cudaGetSymbolAddress((void**)&gA1, g_act1);

    constexpr int SMEM0 = (13232 + 72 + 32) * 4;        // 53.3 KB
    cudaFuncSetAttribute(conv0_kernel,
                         cudaFuncAttributeMaxDynamicSharedMemorySize, SMEM0);
    conv0_kernel<<<dim3(4*11, 16), 297, SMEM0>>>(inp, W0, gA0, bc);

    constexpr int SMEM1 = (27000 + 1440 + 32) * 4;      // 113.9 KB
    cudaFuncSetAttribute(conv1_kernel,
                         cudaFuncAttributeMaxDynamicSharedMemorySize, SMEM1);
    conv1_kernel<<<dim3(3*3, 16), 648, SMEM1>>>(gA0, W1, gA1, bc);

    constexpr int SMEMT = (15926 + 8) * 4;              // 63.7 KB
    cudaFuncSetAttribute(tail_kernel,
                         cudaFuncAttributeMaxDynamicSharedMemorySize, SMEMT);
    tail_kernel<<<16, 256, SMEMT>>>(gA1, W2, fc1w, fc1b, fc2w, fc2b, out, bf);
}

// round 10
// speedup vs baseline: 1.5944x; 1.5944x over previous
#include <cuda_runtime.h>
#include <math.h>

// ---------------------------------------------------------------------------
// Factorized radial-basis CNN. R10 = R6 (best: 151.6us) + ALU surgery only:
//  - conv0: load loop with per-(iy,ix) z-sweep (no per-element div/mod);
//           epilogue stores via base pointer + constexpr channel stride.
//  - conv1: R6 schedule byte-for-byte; epilogue pointer fix only.
//  - fast sigmoid (__expf + __fdividef)  [gates only; tol 1e-3]
//  - kS / head: R6 exact.
// ---------------------------------------------------------------------------

#define PZ 39
#define PX 40
#define PLANE (PZ*PZ*PX)      // 60840 floats per (b,ci) act0 plane

__device__ float g_act0[16*20*PLANE];    // zero-init => halo+pad stay 0
__device__ float g_act1[16*20*18*18*18];
__device__ float g_V[16*20*3];

struct BC { float b[30]; };   // [j*10 + orbit]

__host__ __device__ constexpr int orbit_of(int tz, int ty, int tx) {
    int dz = tz - 2, dy = ty - 2, dx = tx - 2;
    int r2 = dz*dz + dy*dy + dx*dx;            // {0..6, 8, 9, 12}
    return r2 <= 6 ? r2 : (r2 == 8 ? 7 : (r2 == 9 ? 8 : 9));
}

__device__ __forceinline__ void cp_async16(float* dst, const float* src) {
    unsigned int d = (unsigned int)__cvta_generic_to_shared(dst);
    asm volatile("cp.async.cg.shared.global [%0], [%1], 16;" :: "r"(d), "l"(src));
}

__device__ __forceinline__ float fast_sigmoid(float x) {
    return __fdividef(1.f, 1.f + __expf(-x));
}

// ---------------------------------------------------------------------------
// conv0: CIN=1, 64^3 -> 33^3 into padded [39,39,40]. Tile (9z,3y,33x),
// 297 threads; thread: ox=tid%33, oy=(tid/33)%3, zg=tid/99; 3 z-outputs (p).
// ---------------------------------------------------------------------------
__global__ void __launch_bounds__(297)
conv0_kernel(const float* __restrict__ in, const float* __restrict__ W,
             float* __restrict__ out, BC Bc)
{
    extern __shared__ float sm0[];
    float* sIn = sm0;              // 21 z x 9 y x 70 x = 13230
    float* sW  = sm0 + 13232;      // 72, 16B-aligned
    float* sB  = sW + 72;          // 30

    const int tid = threadIdx.x;
    const int b   = blockIdx.y;
    const int zt  = blockIdx.x / 11, yt = blockIdx.x % 11;
    const int oz0 = 9*zt, oy0 = 3*yt;

    if (tid < 72) { int j = tid/24, o = tid%24; sW[tid] = (o < 23) ? W[o*3 + j] : 0.f; }
    if (tid < 30) sB[tid] = Bc.b[tid];

    // ---- tile load: 630 (iy,ix) pairs, each thread sweeps z for its pairs ----
    const float* gin = in + (long)b * (64*64*64);
    {
#pragma unroll
        for (int pr = 0; pr < 3; pr++) {
            int p = tid + 297*pr;
            if (p < 630) {
                int iy = p / 70, ix = p % 70;          // once per pair
                int gy = 2*oy0 - 3 + iy;
                int gx = ix - 3;
                bool yx_ok = (ix < 69) && ((unsigned)gy < 64u) && ((unsigned)gx < 64u);
                const float* gcol = gin + ((2*oz0 - 3)*64 + gy)*64 + gx;
                float* scol = sIn + iy*70 + ix;
#pragma unroll
                for (int iz = 0; iz < 21; iz++) {
                    int gz = 2*oz0 - 3 + iz;
                    float v = 0.f;
                    if (yx_ok && (unsigned)gz < 64u)
                        v = gcol[iz*4096];
                    scol[iz*630] = v;
                }
            }
        }
    }
    __syncthreads();

    const int ox = tid % 33;
    const int r0 = tid / 33;
    const int oy = r0 % 3;
    const int zg = r0 / 3;         // 0..2; thread's z-outputs: oz0+3*zg+p

    float T[3][10];
#pragma unroll
    for (int p = 0; p < 3; p++)
#pragma unroll
        for (int g = 0; g < 10; g++) T[p][g] = 0.f;

#pragma unroll
    for (int s = 0; s < 9; s++) {          // iz = 6*zg + s ; tz = s - 2p
#pragma unroll
        for (int ty = 0; ty < 5; ty++) {
            const float2* rp = (const float2*)
                &sIn[((6*zg + s)*9 + (2*oy + ty))*70 + 2*ox];
            float2 c0 = rp[0], c1 = rp[1], c2 = rp[2];
            float v0 = c0.x, v1 = c0.y, v2 = c1.x, v3 = c1.y, v4 = c2.x;
#pragma unroll
            for (int p = 0; p < 3; p++) {
                const int tz = s - 2*p;
                if (tz >= 0 && tz <= 4) {
                    T[p][orbit_of(tz, ty, 0)] += v0;
                    T[p][orbit_of(tz, ty, 1)] += v1;
                    T[p][orbit_of(tz, ty, 2)] += v2;
                    T[p][orbit_of(tz, ty, 3)] += v3;
                    T[p][orbit_of(tz, ty, 4)] += v4;
                }
            }
        }
    }

    float U[3][3] = {};
#pragma unroll
    for (int j = 0; j < 3; j++)
#pragma unroll
    for (int g = 0; g < 10; g++) {
        float bv = sB[j*10 + g];
        U[0][j] = fmaf(bv, T[0][g], U[0][j]);
        U[1][j] = fmaf(bv, T[1][g], U[1][j]);
        U[2][j] = fmaf(bv, T[2][g], U[2][j]);
    }

    const float4* w4 = (const float4*)sW;
    float* gout = out + (long)b * 20 * PLANE
                + (oy0 + oy + 3)*PX + (ox + 3);
#pragma unroll
    for (int p = 0; p < 3; p++) {
        const int oz = oz0 + 3*zg + p;
        if (oz > 32) continue;
        float y[24];
#pragma unroll
        for (int c = 0; c < 24; c++) y[c] = 0.f;
#pragma unroll
        for (int j = 0; j < 3; j++)
#pragma unroll
        for (int q = 0; q < 6; q++) {
            float4 w = w4[j*6 + q];
            y[q*4+0] = fmaf(U[p][j], w.x, y[q*4+0]);
            y[q*4+1] = fmaf(U[p][j], w.y, y[q*4+1]);
            y[q*4+2] = fmaf(U[p][j], w.z, y[q*4+2]);
            y[q*4+3] = fmaf(U[p][j], w.w, y[q*4+3]);
        }
        float g0 = fast_sigmoid(y[20]);
        float g1 = fast_sigmoid(y[21]);
        float g2 = fast_sigmoid(y[22]);
        float* pb = gout + (long)(oz + 3)*(PZ*PX);   // channel stride = PLANE
#pragma unroll
        for (int oc = 0; oc < 20; oc++) {
            float v = (oc < 5) ? fmaxf(y[oc], 0.f)
                               : y[oc] * (oc < 8 ? g0 : (oc < 13 ? g1 : g2));
            pb[oc*PLANE] = v;
        }
    }
}

// ---------------------------------------------------------------------------
// conv1: CIN=20, act0 [39,39,40] -> 18^3. Tile (6z,6y,18x), 648 threads,
// 1 z-output/thread. Double-buffered contiguous 16B cp.async (R6 schedule).
// ---------------------------------------------------------------------------
__global__ void __launch_bounds__(648, 1)
conv1_kernel(const float* __restrict__ in, const float* __restrict__ W,
             float* __restrict__ out, BC Bc)
{
    constexpr int NT = 648, SLAB = 600;
    extern __shared__ float dsm[];
    float* buf[2] = { dsm, dsm + 9000 };
    float* sW = dsm + 18000;                  // 1440, 16B-aligned
    float* sB = sW + 1440;                    // 30

    const int tid = threadIdx.x;
    const int b   = blockIdx.y;
    const int zt  = blockIdx.x / 3, yt = blockIdx.x % 3;
    const int oz0 = 6*zt, oy0 = 6*yt;

    for (int idx = tid; idx < 1440; idx += NT) {
        int ci = idx / 72, r = idx % 72, j = r / 24, o = r % 24;
        sW[idx] = (o < 23) ? W[(o*20 + ci)*3 + j] : 0.f;
    }
    if (tid < 30) sB[tid] = Bc.b[tid];

    const int ox  = tid % 18;
    const int r0  = tid / 18;
    const int oy  = r0 % 6;
    const int ozl = r0 / 6;        // 0..5

    float acc[24];
#pragma unroll
    for (int c = 0; c < 24; c++) acc[c] = 0.f;

    // 15 slabs; each: 15 y-rows x 40 = 600 contiguous floats in BOTH layouts
    auto issue = [&](int ci, float* dst) {
        const float* g = in + (long)(b*20 + ci)*PLANE
                            + (2*oz0)*(PZ*PX) + (2*oy0)*PX;
        for (int idx = tid; idx < 2250; idx += NT) {      // 15*150 16B-ops
            int iz = idx / 150, k = idx % 150;
            cp_async16(dst + iz*SLAB + 4*k, g + iz*(PZ*PX) + 4*k);
        }
        asm volatile("cp.async.commit_group;");
    };

    issue(0, buf[0]);
    for (int ci = 0; ci < 20; ci++) {
        float* cur = buf[ci & 1];
        if (ci + 1 < 20) {
            issue(ci + 1, buf[(ci + 1) & 1]);
            asm volatile("cp.async.wait_group 1;");
        } else {
            asm volatile("cp.async.wait_group 0;");
        }
        __syncthreads();

        float T[10];
#pragma unroll
        for (int g = 0; g < 10; g++) T[g] = 0.f;

#pragma unroll
        for (int tz = 0; tz < 5; tz++) {
#pragma unroll
            for (int ty = 0; ty < 5; ty++) {
                const float2* rp = (const float2*)
                    &cur[(2*ozl + tz)*SLAB + (2*oy + ty)*PX + 2*ox];
                float2 c0 = rp[0], c1 = rp[1], c2 = rp[2];
                T[orbit_of(tz, ty, 0)] += c0.x;
                T[orbit_of(tz, ty, 1)] += c0.y;
                T[orbit_of(tz, ty, 2)] += c1.x;
                T[orbit_of(tz, ty, 3)] += c1.y;
                T[orbit_of(tz, ty, 4)] += c2.x;
            }
        }

        float U[3] = {};
#pragma unroll
        for (int j = 0; j < 3; j++)
#pragma unroll
        for (int g = 0; g < 10; g++)
            U[j] = fmaf(sB[j*10 + g], T[g], U[j]);

        const float4* w4 = (const float4*)&sW[ci*72];
#pragma unroll
        for (int j = 0; j < 3; j++)
#pragma unroll
        for (int q = 0; q < 6; q++) {
            float4 w = w4[j*6 + q];
            acc[q*4+0] = fmaf(U[j], w.x, acc[q*4+0]);
            acc[q*4+1] = fmaf(U[j], w.y, acc[q*4+1]);
            acc[q*4+2] = fmaf(U[j], w.z, acc[q*4+2]);
            acc[q*4+3] = fmaf(U[j], w.w, acc[q*4+3]);
        }
        __syncthreads();   // protect buffer reuse
    }

    const int oz = oz0 + ozl;
    float* pb = out + (long)b * 20 * 5832
              + (long)oz*324 + (oy0 + oy)*18 + ox;      // channel stride 5832
    float g0 = fast_sigmoid(acc[20]);
    float g1 = fast_sigmoid(acc[21]);
    float g2 = fast_sigmoid(acc[22]);
#pragma unroll
    for (int oc = 0; oc < 20; oc++) {
        float y = acc[oc];
        float v = (oc < 5) ? fmaxf(y, 0.f)
                           : y * (oc < 8 ? g0 : (oc < 13 ? g1 : g2));
        pb[oc*5832] = v;
    }
}

// ---------------------------------------------------------------------------
// kS + fused B-contraction: V[b,ci,j] = sum_t B[j,orbit(t)] * S_t   (R6 exact)
// ---------------------------------------------------------------------------
__global__ void kS_kernel(const float* __restrict__ act, float* __restrict__ V,
                          BC Bc) {
    __shared__ float s[5832];
    __shared__ float R[1620];     // [z][y][tx]
    __shared__ float sS[128];
    int ci = blockIdx.x;
    int b  = blockIdx.y;
    int tid = threadIdx.x;        // 128
    const float* p = act + (long)(b*20 + ci) * 5832;
    for (int i = tid; i < 5832; i += 128) s[i] = p[i];
    __syncthreads();

    for (int idx = tid; idx < 1620; idx += 128) {
        int z = idx / 90, r = idx % 90, y = r / 5, tx = r % 5;
        int lo = (3 - tx + 1) >> 1; if (lo < 0) lo = 0;
        int hi = (20 - tx) >> 1;    if (hi > 9) hi = 9;
        float sum = 0.f;
        const float* row = &s[(z*18 + y)*18];
        for (int oxx = lo; oxx <= hi; oxx++) sum += row[2*oxx + tx - 3];
        R[idx] = sum;
    }
    __syncthreads();

    if (tid < 125) {
        int tz = tid / 25, ty = (tid / 5) % 5, tx = tid % 5;
        int loz = (3 - tz + 1) >> 1; if (loz < 0) loz = 0;
        int hiz = (20 - tz) >> 1;    if (hiz > 9) hiz = 9;
        int loy = (3 - ty + 1) >> 1; if (loy < 0) loy = 0;
        int hiy = (20 - ty) >> 1;    if (hiy > 9) hiy = 9;
        float sum = 0.f;
        for (int oz = loz; oz <= hiz; oz++) {
            int z = 2*oz + tz - 3;
            for (int oyy = loy; oyy <= hiy; oyy++)
                sum += R[((z)*18 + (2*oyy + ty - 3))*5 + tx];
        }
        sS[tid] = sum;
    }
    __syncthreads();

    if (tid < 3) {
        float a = 0.f;
        for (int t = 0; t < 125; t++) {
            int tz = t / 25, ty = (t / 5) % 5, tx = t % 5;
            a = fmaf(Bc.b[tid*10 + orbit_of(tz, ty, tx)], sS[t], a);
        }
        V[(b*20 + ci)*3 + tid] = a;
    }
}

// ---------------------------------------------------------------------------
// head: one block per batch element (16 blocks x 64 threads).  (R6 exact)
// ---------------------------------------------------------------------------
__global__ void head_kernel(const float* __restrict__ V, const float* __restrict__ W2,
                            const float* __restrict__ fc1w, const float* __restrict__ fc1b,
                            const float* __restrict__ fc2w, const float* __restrict__ fc2b,
                            float* __restrict__ out)
{
    __shared__ float sV[60];
    __shared__ float sW2[1380];
    __shared__ float sF1[1000];
    __shared__ float pooled[20];
    __shared__ float h1[50];
    const int b = blockIdx.x;
    const int t = threadIdx.x;     // 64
    if (t < 60) sV[t] = V[b*60 + t];
    for (int i = t; i < 1380; i += 64) sW2[i] = W2[i];
    for (int i = t; i < 1000; i += 64) sF1[i] = fc1w[i];
    __syncthreads();
    if (t < 20) {
        float a = 0.f;
        for (int k = 0; k < 60; k++)
            a = fmaf(sW2[t*60 + k], sV[k], a);
        pooled[t] = a * (1.0f/1000.0f);
    }
    __syncthreads();
    if (t < 50) {
        float a = fc1b[t];
        for (int k = 0; k < 20; k++)
            a = fmaf(pooled[k], sF1[t*20 + k], a);
        h1[t] = fmaxf(a, 0.f);
    }
    __syncthreads();
    if (t < 2) {
        float a = fc2b[t];
        for (int k = 0; k < 50; k++)
            a = fmaf(h1[k], fc2w[t*50 + k], a);
        out[b*2 + t] = a;
    }
}

// ---------------------------------------------------------------------------
extern "C" void kernel_launch(void* const* d_in, const int* in_sizes, int n_in,
                              void* d_out, int out_size) {
    const float* inp  = (const float*)d_in[0];
    const float* W0   = (const float*)d_in[1];
    const float* W1   = (const float*)d_in[2];
    const float* W2   = (const float*)d_in[3];
    const float* fc1w = (const float*)d_in[4];
    const float* fc1b = (const float*)d_in[5];
    const float* fc2w = (const float*)d_in[6];
    const float* fc2b = (const float*)d_in[7];
    float* out = (float*)d_out;

    BC bc;
    {
        const double r2s[10]  = {0,1,2,3,4,5,6,8,9,12};
        const double mult[10] = {1,6,12,8,6,24,24,12,24,8};
        for (int j = 0; j < 3; j++) {
            double v[10], sm = 0.0;
            for (int g = 0; g < 10; g++) {
                double d = (sqrt(r2s[g]) - (double)j) / 0.6;
                v[g] = exp(-0.5 * d * d);
                sm += mult[g] * v[g] * v[g];
            }
            double inv = 1.0 / sqrt(sm);
            for (int g = 0; g < 10; g++) bc.b[j*10 + g] = (float)(v[g] * inv);
        }
    }

    float *gA0, *gA1, *gV;
    cudaGetSymbolAddress((void**)&gA0, g_act0);
    cudaGetSymbolAddress((void**)&gA1, g_act1);
    cudaGetSymbolAddress((void**)&gV,  g_V);

    constexpr int SMEM0 = (13232 + 72 + 32) * 4;        // 53.3 KB
    cudaFuncSetAttribute(conv0_kernel,
                         cudaFuncAttributeMaxDynamicSharedMemorySize, SMEM0);
    conv0_kernel<<<dim3(4*11, 16), 297, SMEM0>>>(inp, W0, gA0, bc);

    constexpr int SMEM1 = (18000 + 1440 + 32) * 4;      // 77.9 KB
    cudaFuncSetAttribute(conv1_kernel,
                         cudaFuncAttributeMaxDynamicSharedMemorySize, SMEM1);
    conv1_kernel<<<dim3(3*3, 16), 648, SMEM1>>>(gA0, W1, gA1, bc);

    kS_kernel<<<dim3(20, 16), 128>>>(gA1, gV, bc);
    head_kernel<<<16, 64>>>(gV, W2, fc1w, fc1b, fc2w, fc2b, out);
}